// round 16
// baseline (speedup 1.0000x reference)
#include <cuda_runtime.h>
#include <cuda_bf16.h>
#include <cuda_fp16.h>
#include <math.h>
#include <stdint.h>

// Problem constants
constexpr int B_ = 512;
constexpr int T_ = 256;
constexpr int C_ = 384;   // n_embd
constexpr int H_ = 64;    // head_size
constexpr int BT_ = B_ * T_;          // 131072 rows
constexpr float QS_ = 0.05103103630798287f * 1.44269504088896341f;  // 384^-0.5 * log2(e)

// Packed projection outputs, fp16 pairs (32 u32 per row = 64 halves)
__device__ uint32_t g_q16[(size_t)BT_ * 32];   // Q, scale*log2e folded
__device__ uint32_t g_k16[(size_t)BT_ * 32];
__device__ uint32_t g_v16[(size_t)BT_ * 32];

// Pre-converted W (fp16), proj SMEM tile layout: [chunk][k 0..31][n 0..199]
__device__ uint16_t g_w16[12 * 32 * 200];

// ---------------------------------------------------------------------------
// helpers
// ---------------------------------------------------------------------------
__device__ __forceinline__ void mma_fp16(float* d, const uint32_t* a, const uint32_t* b)
{
    asm volatile(
        "mma.sync.aligned.m16n8k16.row.col.f32.f16.f16.f32 "
        "{%0,%1,%2,%3}, {%4,%5,%6,%7}, {%8,%9}, {%0,%1,%2,%3};"
        : "+f"(d[0]), "+f"(d[1]), "+f"(d[2]), "+f"(d[3])
        : "r"(a[0]), "r"(a[1]), "r"(a[2]), "r"(a[3]), "r"(b[0]), "r"(b[1]));
}
__device__ __forceinline__ void ldmx4(uint32_t& r0, uint32_t& r1, uint32_t& r2, uint32_t& r3,
                                      uint32_t addr)
{
    asm volatile("ldmatrix.sync.aligned.m8n8.x4.shared.b16 {%0,%1,%2,%3}, [%4];"
                 : "=r"(r0), "=r"(r1), "=r"(r2), "=r"(r3) : "r"(addr));
}
__device__ __forceinline__ void ldmx4t(uint32_t& r0, uint32_t& r1, uint32_t& r2, uint32_t& r3,
                                       uint32_t addr)
{
    asm volatile("ldmatrix.sync.aligned.m8n8.x4.trans.shared.b16 {%0,%1,%2,%3}, [%4];"
                 : "=r"(r0), "=r"(r1), "=r"(r2), "=r"(r3) : "r"(addr));
}
__device__ __forceinline__ uint32_t smem_u32(const void* p) {
    uint32_t a;
    asm("{ .reg .u64 t; cvta.to.shared.u64 t, %1; cvt.u32.u64 %0, t; }" : "=r"(a) : "l"(p));
    return a;
}
__device__ __forceinline__ void cp16(uint32_t dst, const void* src) {
    asm volatile("cp.async.cg.shared.global [%0], [%1], 16;" :: "r"(dst), "l"(src) : "memory");
}
#define CP_COMMIT() asm volatile("cp.async.commit_group;" ::: "memory")
#define CP_WAIT0()  asm volatile("cp.async.wait_group 0;" ::: "memory")

__device__ __forceinline__ float ex2f(float x) {
    float r; asm("ex2.approx.f32 %0, %1;" : "=f"(r) : "f"(x)); return r;
}
__device__ __forceinline__ uint32_t ex2_f16x2(float lo, float hi) {
    uint32_t t;
    asm("cvt.rn.f16x2.f32 %0, %1, %2;" : "=r"(t) : "f"(hi), "f"(lo));
    asm("ex2.approx.f16x2 %0, %0;" : "+r"(t));
    return t;
}
__device__ __forceinline__ uint32_t pack_fp16(float a, float b) {
    return ((uint32_t)__half_as_ushort(__float2half_rn(b)) << 16) |
            (uint32_t)__half_as_ushort(__float2half_rn(a));
}

// ---------------------------------------------------------------------------
// Kernel 0: W fp32 -> fp16, proj SMEM tile layout.
// ---------------------------------------------------------------------------
__global__ __launch_bounds__(256) void wsplit_kernel(
    const float* __restrict__ Wq, const float* __restrict__ Wk, const float* __restrict__ Wv)
{
    const int idx = blockIdx.x * 256 + threadIdx.x;
    if (idx >= 12 * 32 * 192) return;
    const int ch  = idx / (32 * 192);
    const int rem = idx % (32 * 192);
    const int k   = rem / 192;
    const int n   = rem % 192;
    const int mat = n >> 6, h = n & 63;
    const float* W = (mat == 0) ? Wq : (mat == 1) ? Wk : Wv;
    g_w16[ch * 6400 + k * 200 + n] =
        __half_as_ushort(__float2half_rn(W[(size_t)(ch * 32 + k) * H_ + h]));
}

// ---------------------------------------------------------------------------
// Kernel 1: fused QKV projection, single fp16 HMMA.
// CTA tile 64x192, 8 warps (2x4), K chunks of 32, double-buffered.
// ---------------------------------------------------------------------------
constexpr int PM = 64;
constexpr int KC = 32;
constexpr int NCH = C_ / KC;     // 12
constexpr int RSTA = 40;
constexpr int RSTB = 200;

constexpr int A_OFF = 0;
constexpr int B_OFF = PM * RSTA;                  // 2560
constexpr int BUF_HALVES = B_OFF + KC * RSTB;     // 8960

__global__ __launch_bounds__(256) void proj_mma_kernel(
    const float* __restrict__ x,
    const float* __restrict__ bq, const float* __restrict__ bk, const float* __restrict__ bv)
{
    __shared__ __align__(16) uint16_t sm[2 * BUF_HALVES];   // 35840 B
    const uint32_t smBase = smem_u32(sm);

    const int tid = threadIdx.x;
    const int w   = tid >> 5;
    const int l   = tid & 31;
    const int wm  = w >> 2;          // 0..1 (32-row band)
    const int wn  = w & 3;           // 0..3 (48-col band)
    const int row0 = blockIdx.x * PM;

    const int lq = l >> 2;
    const int lr = (l & 3) * 2;
    const int trow = l & 7;
    const int tq   = l >> 3;

    float acc[2][6][4];
#pragma unroll
    for (int i = 0; i < 2; i++)
#pragma unroll
        for (int j = 0; j < 6; j++)
#pragma unroll
            for (int r = 0; r < 4; r++) acc[i][j][r] = 0.f;

    float4 ra[2];

    auto loadA = [&](int ch) {
#pragma unroll
        for (int t = 0; t < 2; t++) {
            const int i = tid + t * 256;        // 0..511
            const int r = i >> 3;
            const int q = i & 7;
            ra[t] = *reinterpret_cast<const float4*>(
                x + (size_t)(row0 + r) * C_ + ch * KC + q * 4);
        }
    };
    auto cvtA_store = [&](int buf) {
        uint16_t* A = sm + buf * BUF_HALVES + A_OFF;
#pragma unroll
        for (int t = 0; t < 2; t++) {
            const int i = tid + t * 256;
            const int r = i >> 3;
            const int q = i & 7;
            uint2 hp;
            hp.x = pack_fp16(ra[t].x, ra[t].y);
            hp.y = pack_fp16(ra[t].z, ra[t].w);
            *reinterpret_cast<uint2*>(A + r * RSTA + q * 4) = hp;
        }
    };
    auto copyB = [&](int ch, int buf) {
        const uint32_t dst = smBase + (uint32_t)(buf * BUF_HALVES + B_OFF) * 2u;
        const uint16_t* src = g_w16 + ch * 6400;
#pragma unroll
        for (int t = 0; t < 3; t++) {
            const int i = tid + t * 256;     // 0..767
            const int k   = i / 24;
            const int seg = i % 24;
            cp16(dst + (uint32_t)(k * RSTB + seg * 8) * 2u, src + k * 200 + seg * 8);
        }
    };
    auto compute = [&](int buf) {
        const uint32_t base = smBase + (uint32_t)(buf * BUF_HALVES) * 2u;
        const uint32_t aA = base + A_OFF * 2;
        const uint32_t bA = base + B_OFF * 2;
#pragma unroll
        for (int kt = 0; kt < 2; kt++) {
            uint32_t bh[6][2];
#pragma unroll
            for (int jp = 0; jp < 3; jp++) {
                const int n0 = wn * 48 + jp * 16;
                const uint32_t off =
                    (uint32_t)((kt * 16 + (tq & 1) * 8 + trow) * RSTB + n0 + (tq >> 1) * 8) * 2u;
                uint32_t r0, r1, r2, r3;
                ldmx4t(r0, r1, r2, r3, bA + off);
                bh[jp*2][0] = r0; bh[jp*2][1] = r1;
                bh[jp*2+1][0] = r2; bh[jp*2+1][1] = r3;
            }
#pragma unroll
            for (int i = 0; i < 2; i++) {
                const int rbase = wm * 32 + i * 16;
                const uint32_t aoff =
                    (uint32_t)((rbase + (tq & 1) * 8 + trow) * RSTA + kt * 16 + (tq >> 1) * 8) * 2u;
                uint32_t a[4];
                ldmx4(a[0], a[1], a[2], a[3], aA + aoff);
#pragma unroll
                for (int j = 0; j < 6; j++)
                    mma_fp16(acc[i][j], a, bh[j]);
            }
        }
    };

    loadA(0);
    copyB(0, 0); CP_COMMIT();
    cvtA_store(0);
    for (int ch = 0; ch < NCH; ch++) {
        const int buf = ch & 1;
        CP_WAIT0();
        __syncthreads();
        if (ch + 1 < NCH) {
            copyB(ch + 1, buf ^ 1); CP_COMMIT();
            loadA(ch + 1);
        }
        compute(buf);
        if (ch + 1 < NCH) cvtA_store(buf ^ 1);
    }

    // epilogue: bias + pack fp16 outputs
#pragma unroll
    for (int j = 0; j < 6; j++) {
        const int n0 = wn * 48 + j * 8 + lr;
        const int mat = n0 >> 6;
        const int nn  = n0 & 63;
        const float* bias = (mat == 0) ? bq : (mat == 1) ? bk : bv;
        const float b0 = bias[nn], b1 = bias[nn + 1];
        uint32_t* dst = (mat == 0) ? g_q16 : (mat == 1) ? g_k16 : g_v16;
        const float s = (mat == 0) ? QS_ : 1.f;
#pragma unroll
        for (int i = 0; i < 2; i++) {
            const int r = row0 + wm * 32 + i * 16 + lq;
#pragma unroll
            for (int rh = 0; rh < 2; rh++) {
                const size_t oidx = (size_t)(r + rh * 8) * 32 + nn / 2;
                const float v0 = (acc[i][j][rh * 2 + 0] + b0) * s;
                const float v1 = (acc[i][j][rh * 2 + 1] + b1) * s;
                dst[oidx] = pack_fp16(v0, v1);
            }
        }
    }
}

// ---------------------------------------------------------------------------
// Kernel 2: flash attention, single fp16 HMMA. 4 warps / 64 queries per CTA.
// Diagonal tiles skip fully-masked column groups (warp-uniform bounds).
// 4 CTAs/SM forced via launch_bounds.
// ---------------------------------------------------------------------------
constexpr int ABM = 64;
constexpr int ABN = 64;
constexpr int KVR = 72;
constexpr int S_K  = 0;
constexpr int S_V  = ABN * KVR;        // 4608 halves
constexpr int S_BUF = 2 * ABN * KVR;   // 9216 halves
constexpr int SMEM_ATTN_BYTES = 2 * S_BUF * 2;   // 36864

__global__ __launch_bounds__(128, 4) void attn_mma_kernel(float* __restrict__ out)
{
    extern __shared__ __align__(16) uint16_t sma[];
    const uint32_t smaA = smem_u32(sma);

    const int tid = threadIdx.x;
    const int w   = tid >> 5;
    const int l   = tid & 31;
    const int lq  = l >> 2;
    const int lr  = (l & 3) * 2;

    const int mt  = blockIdx.x;          // query tile (fast dim -> wave mixing)
    const int bb  = blockIdx.y;          // batch
    const int q0  = mt * ABM + w * 16;
    const size_t rbase = (size_t)bb * T_;

    // Q fragments (pre-scaled fp16)
    uint32_t qf[4][4];
    {
        const uint32_t* qp = g_q16 + rbase * 32;
#pragma unroll
        for (int kt = 0; kt < 4; kt++)
#pragma unroll
            for (int half = 0; half < 2; half++)
#pragma unroll
                for (int rh = 0; rh < 2; rh++) {
                    const int r = q0 + lq + rh * 8;
                    qf[kt][rh + half * 2] = qp[(size_t)r * 32 + kt * 8 + (l & 3) + half * 4];
                }
    }

    float o[8][4];
#pragma unroll
    for (int n = 0; n < 8; n++)
#pragma unroll
        for (int r = 0; r < 4; r++) o[n][r] = 0.f;
    float mrow[2] = {-1e30f, -1e30f};
    float lrow[2] = {0.f, 0.f};

    auto stage = [&](int j, int buf) {
        const uint32_t dst = smaA + (uint32_t)(buf * S_BUF) * 2u;
        const size_t row = rbase + (size_t)j * ABN;
#pragma unroll
        for (int t = 0; t < 4; t++) {
            const int i = tid + t * 128;     // 0..511
            const int key = i >> 3;
            const int seg = i & 7;
            const uint32_t doff = (uint32_t)(key * KVR + seg * 8) * 2u;
            cp16(dst + S_K * 2 + doff, g_k16 + (row + key) * 32 + seg * 4);
            cp16(dst + S_V * 2 + doff, g_v16 + (row + key) * 32 + seg * 4);
        }
    };

    const int ntiles = mt + 1;
    stage(0, 0); CP_COMMIT();

    const uint32_t onesb[2] = {0x3C003C00u, 0x3C003C00u};   // f16 1.0 x4

    const int klm   = l >> 3;        // ldmatrix matrix select
    const int klrow = l & 7;

    for (int j = 0; j < ntiles; j++) {
        const int buf = j & 1;
        CP_WAIT0();
        __syncthreads();
        if (j + 1 < ntiles) { stage(j + 1, buf ^ 1); CP_COMMIT(); }

        const uint32_t ksA = smaA + (uint32_t)(buf * S_BUF + S_K) * 2u;
        const uint32_t vsA = smaA + (uint32_t)(buf * S_BUF + S_V) * 2u;

        // Diagonal tile: warp w only needs key columns <= w*16+15.
        const bool diag = (j == mt);
        const int pv  = diag ? (w + 1) : 4;     // valid p groups (16 cols each)
        const int ktv = diag ? (w + 1) : 4;     // valid PV k-groups (16 keys each)
        const int ntv = 2 * pv;                 // valid nt (8-col groups)

        // scores — K b-frags via ldmatrix.x4 non-trans
        float c[8][4];
#pragma unroll
        for (int p = 0; p < 4; p++) {
            if (p >= pv) break;
            const int n_row = p * 16 + (klm >> 1) * 8 + klrow;
#pragma unroll
            for (int r = 0; r < 4; r++) { c[2*p][r] = 0.f; c[2*p+1][r] = 0.f; }
#pragma unroll
            for (int kt = 0; kt < 4; kt++) {
                const uint32_t addr = ksA +
                    (uint32_t)(n_row * KVR + kt * 16 + (klm & 1) * 8) * 2u;
                uint32_t b0, b1, b2, b3;
                ldmx4(b0, b1, b2, b3, addr);
                uint32_t bA[2] = {b0, b1};
                uint32_t bB[2] = {b2, b3};
                mma_fp16(c[2*p],     qf[kt], bA);
                mma_fp16(c[2*p + 1], qf[kt], bB);
            }
        }

        // causal mask (diagonal tile only, valid nt only)
        if (diag) {
#pragma unroll
            for (int nt = 0; nt < 8; nt++) {
                if (nt >= ntv) break;
                const int col = j * ABN + nt * 8 + lr;
                const int r0 = q0 + lq, r1 = q0 + lq + 8;
                if (col > r0)     c[nt][0] = -1e30f;
                if (col + 1 > r0) c[nt][1] = -1e30f;
                if (col > r1)     c[nt][2] = -1e30f;
                if (col + 1 > r1) c[nt][3] = -1e30f;
            }
        }

        // row max (quad reduction) over valid nt
        float tm0 = -1e30f, tm1 = -1e30f;
#pragma unroll
        for (int nt = 0; nt < 8; nt++) {
            if (nt >= ntv) break;
            tm0 = fmaxf(tm0, fmaxf(c[nt][0], c[nt][1]));
            tm1 = fmaxf(tm1, fmaxf(c[nt][2], c[nt][3]));
        }
        tm0 = fmaxf(tm0, __shfl_xor_sync(0xffffffffu, tm0, 1));
        tm0 = fmaxf(tm0, __shfl_xor_sync(0xffffffffu, tm0, 2));
        tm1 = fmaxf(tm1, __shfl_xor_sync(0xffffffffu, tm1, 1));
        tm1 = fmaxf(tm1, __shfl_xor_sync(0xffffffffu, tm1, 2));

        const float mn0 = fmaxf(mrow[0], tm0);
        const float mn1 = fmaxf(mrow[1], tm1);
        const float corr0 = ex2f(mrow[0] - mn0);
        const float corr1 = ex2f(mrow[1] - mn1);
        mrow[0] = mn0; mrow[1] = mn1;

        // P fragments via f16x2 exp2, valid kt groups only
        uint32_t pf[4][4];
#pragma unroll
        for (int kt = 0; kt < 4; kt++) {
            if (kt >= ktv) break;
            pf[kt][0] = ex2_f16x2(c[2*kt][0]   - mn0, c[2*kt][1]   - mn0);
            pf[kt][1] = ex2_f16x2(c[2*kt][2]   - mn1, c[2*kt][3]   - mn1);
            pf[kt][2] = ex2_f16x2(c[2*kt+1][0] - mn0, c[2*kt+1][1] - mn0);
            pf[kt][3] = ex2_f16x2(c[2*kt+1][2] - mn1, c[2*kt+1][3] - mn1);
        }

        // row sums via ones-MMA (valid kt only)
        float ss[4] = {0.f, 0.f, 0.f, 0.f};
#pragma unroll
        for (int kt = 0; kt < 4; kt++) {
            if (kt >= ktv) break;
            mma_fp16(ss, pf[kt], onesb);
        }
        lrow[0] = lrow[0] * corr0 + ss[0];
        lrow[1] = lrow[1] * corr1 + ss[2];

#pragma unroll
        for (int n = 0; n < 8; n++) {
            o[n][0] *= corr0; o[n][1] *= corr0;
            o[n][2] *= corr1; o[n][3] *= corr1;
        }

        // PV via ldmatrix.x4.trans (valid kt groups only)
#pragma unroll
        for (int kt = 0; kt < 4; kt++) {
            if (kt >= ktv) break;
#pragma unroll
            for (int dp = 0; dp < 4; dp++) {
                const uint32_t off =
                    (uint32_t)((kt * 16 + (klm & 1) * 8 + klrow) * KVR + dp * 16 + (klm >> 1) * 8) * 2u;
                uint32_t b0, b1, b2, b3;
                ldmx4t(b0, b1, b2, b3, vsA + off);
                uint32_t bA[2] = {b0, b1};
                uint32_t bB[2] = {b2, b3};
                mma_fp16(o[2*dp],     pf[kt], bA);
                mma_fp16(o[2*dp + 1], pf[kt], bB);
            }
        }
    }

    // epilogue
    const float inv0 = 1.f / lrow[0];
    const float inv1 = 1.f / lrow[1];
    const int r0 = q0 + lq, r1 = q0 + lq + 8;
#pragma unroll
    for (int nt = 0; nt < 8; nt++) {
        float2 v0, v1;
        v0.x = o[nt][0] * inv0; v0.y = o[nt][1] * inv0;
        v1.x = o[nt][2] * inv1; v1.y = o[nt][3] * inv1;
        *reinterpret_cast<float2*>(out + (rbase + r0) * H_ + nt * 8 + lr) = v0;
        *reinterpret_cast<float2*>(out + (rbase + r1) * H_ + nt * 8 + lr) = v1;
    }
}

// ---------------------------------------------------------------------------
// Launch
// ---------------------------------------------------------------------------
extern "C" void kernel_launch(void* const* d_in, const int* in_sizes, int n_in,
                              void* d_out, int out_size)
{
    const float* x  = (const float*)d_in[0];
    const float* Wq = (const float*)d_in[1];
    const float* bq = (const float*)d_in[2];
    const float* Wk = (const float*)d_in[3];
    const float* bk = (const float*)d_in[4];
    const float* Wv = (const float*)d_in[5];
    const float* bv = (const float*)d_in[6];
    float* out = (float*)d_out;

    static bool attr_set = false;
    if (!attr_set) {
        cudaFuncSetAttribute(attn_mma_kernel,
                             cudaFuncAttributeMaxDynamicSharedMemorySize, SMEM_ATTN_BYTES);
        attr_set = true;
    }

    wsplit_kernel<<<(12 * 32 * 192 + 255) / 256, 256>>>(Wq, Wk, Wv);
    proj_mma_kernel<<<BT_ / PM, 256>>>(x, bq, bk, bv);

    dim3 grid(T_ / ABM, B_);
    attn_mma_kernel<<<grid, 128, SMEM_ATTN_BYTES>>>(out);
}